// round 3
// baseline (speedup 1.0000x reference)
#include <cuda_runtime.h>

// BaseTextureDiffusion: out[b,c,h,w] = sum_{k=0..48} weights[b,c,k,h,w] *
//                       latent_edgepadded[b,c, h+k/7-3, w+k%7-3]
// Shapes: latent (2,24,256,256) f32, weights (2,24,49,256,256) f32, R=7.
//
// HBM-bound on the 616MB read-once weights stream.
// R3 changes vs R2 (96.7us, DRAM 80.4%, occ-6 -> 3.46 waves):
//  - Persistent single-wave launch: 768 blocks (all resident at occ 6),
//    each handles exactly 4 tiles (3072/768) via grid-stride. Removes the
//    partial-wave tail that was averaging DRAM down to 80%.
//  - Keeps __ldcs streaming weights, __stcs output, 7-deep MLP batching.

#define BB 2
#define CC 24
#define HH 256
#define WW 256
#define RR 7
#define PAD 3
#define HW (HH * WW)

#define TILE_ROWS 4                   // output rows per tile
#define TILES_H (HH / TILE_ROWS)      // 64
#define NTILES (BB * CC * TILES_H)    // 3072
#define GRIDSZ 768                    // NTILES / GRIDSZ == 4 exactly
#define SROWS (TILE_ROWS + 2 * PAD)   // 10
#define SCOLS 264                     // latent cols -4..259

__global__ __launch_bounds__(256, 6)
void texdiff_kernel(const float* __restrict__ latent,
                    const float* __restrict__ weights,
                    float* __restrict__ out)
{
    __shared__ float tile[SROWS][SCOLS];

    const int x   = threadIdx.x;               // 0..63 : float4 lane over w
    const int y   = threadIdx.y;               // 0..3  : row within tile
    const int tid = y * 64 + x;                // 0..255
    const int w0  = 4 * x;

    #pragma unroll
    for (int t = blockIdx.x; t < NTILES; t += GRIDSZ) {
        const int bc = t / TILES_H;            // 0..47
        const int h0 = (t - bc * TILES_H) * TILE_ROWS;

        const float* lat = latent + (long)bc * HW;

        // Stage latent tile with edge clamp:
        // tile[r][cix] = latent[clamp(h0 + r - 3), clamp(cix - 4)]
        #pragma unroll
        for (int idx = tid; idx < SROWS * SCOLS; idx += 256) {
            int r   = idx / SCOLS;
            int cix = idx - r * SCOLS;
            int gh  = h0 + r - PAD;
            gh = gh < 0 ? 0 : (gh > HH - 1 ? HH - 1 : gh);
            int gw  = cix - 4;
            gw = gw < 0 ? 0 : (gw > WW - 1 ? WW - 1 : gw);
            tile[r][cix] = lat[gh * WW + gw];
        }
        __syncthreads();

        const int h = h0 + y;
        const float* wbase = weights + (long)bc * (RR * RR) * HW + h * WW + w0;

        float4 acc = make_float4(0.f, 0.f, 0.f, 0.f);

        #pragma unroll
        for (int i = 0; i < RR; i++) {
            // Batch: 7 weight vectors for this window row, streaming loads.
            float4 wv[RR];
            #pragma unroll
            for (int j = 0; j < RR; j++)
                wv[j] = __ldcs((const float4*)(wbase + (long)(i * RR + j) * HW));

            // 12 consecutive latent values covering cols w0-3 .. w0+8
            const float4* srow = (const float4*)&tile[y + i][w0];
            float4 a = srow[0];
            float4 b = srow[1];
            float4 c = srow[2];
            float r[12] = { a.x, a.y, a.z, a.w,
                            b.x, b.y, b.z, b.w,
                            c.x, c.y, c.z, c.w };

            #pragma unroll
            for (int j = 0; j < RR; j++) {
                acc.x += wv[j].x * r[1 + j];
                acc.y += wv[j].y * r[2 + j];
                acc.z += wv[j].z * r[3 + j];
                acc.w += wv[j].w * r[4 + j];
            }
        }

        __stcs((float4*)(out + (long)bc * HW + h * WW + w0), acc);

        __syncthreads();   // protect smem tile before next iteration's staging
    }
}

extern "C" void kernel_launch(void* const* d_in, const int* in_sizes, int n_in,
                              void* d_out, int out_size)
{
    const float* latent  = (const float*)d_in[0];
    const float* weights = (const float*)d_in[1];
    // d_in[2] = window_size (int scalar, always 7 here)
    float* out = (float*)d_out;

    dim3 block(64, TILE_ROWS, 1);
    dim3 grid(GRIDSZ, 1, 1);
    texdiff_kernel<<<grid, block>>>(latent, weights, out);
}